// round 16
// baseline (speedup 1.0000x reference)
#include <cuda_runtime.h>
#include <cuda_fp16.h>
#include <math.h>
#include <cstdint>

// Problem constants
#define B_ 4
#define S_ 2048
#define D_ 1024
#define H_ 16
#define DH_ 64
#define DFF_ 4096

// Scratch layout
// float region (floats)
#define OFF_PROJ  0LL
#define OFF_LN1   8388608LL
#define OFF_MLP   16777216LL
#define FLOAT_END 25165824LL
// half region (halves, from hbase). Packed operands use tile layout:
// [rblk][kblk][128 rows][72 halves] (64 data + 8 pad), tile = 9216 halves.
#define HOFF_Q     0LL
#define HOFF_K     8388608LL
#define HOFF_V     16777216LL
#define HOFF_ATT   25165824LL
#define HOFF_X     34603008LL
#define HOFF_LN1   44040192LL
#define HOFF_WQKV  53477376LL
#define HOFF_WPROJ 57016320LL
#define HOFF_W1    58195968LL
#define HOFF_W2    62914560LL
#define HOFF_FFH   67633152LL
#define HALF_END   105381888LL
#define SCRATCH_TOTAL (FLOAT_END + HALF_END / 2)   // 77856768 floats

__device__ __align__(256) float g_scratch[SCRATCH_TOTAL];

// ---------------------------------------------------------------------------
// helpers
// ---------------------------------------------------------------------------
__device__ __forceinline__ void mma_f16(float c[4], const uint32_t a[4], const uint32_t b[2]) {
    asm volatile(
        "mma.sync.aligned.m16n8k16.row.col.f32.f16.f16.f32 "
        "{%0,%1,%2,%3}, {%4,%5,%6,%7}, {%8,%9}, {%0,%1,%2,%3};"
        : "+f"(c[0]), "+f"(c[1]), "+f"(c[2]), "+f"(c[3])
        : "r"(a[0]), "r"(a[1]), "r"(a[2]), "r"(a[3]),
          "r"(b[0]), "r"(b[1]));
}

__device__ __forceinline__ void ldm_x4(uint32_t r[4], uint32_t addr) {
    asm volatile("ldmatrix.sync.aligned.m8n8.x4.shared.b16 {%0,%1,%2,%3}, [%4];"
        : "=r"(r[0]), "=r"(r[1]), "=r"(r[2]), "=r"(r[3]) : "r"(addr));
}
__device__ __forceinline__ void ldm_x4t(uint32_t r[4], uint32_t addr) {
    asm volatile("ldmatrix.sync.aligned.m8n8.x4.trans.shared.b16 {%0,%1,%2,%3}, [%4];"
        : "=r"(r[0]), "=r"(r[1]), "=r"(r[2]), "=r"(r[3]) : "r"(addr));
}

// 1D bulk async copy global->shared with mbarrier completion (sm_90 base)
__device__ __forceinline__ void cp_bulk(uint32_t dst_smem, const void* src,
                                        uint32_t bytes, uint32_t mbar) {
    asm volatile(
        "cp.async.bulk.shared::cluster.global.mbarrier::complete_tx::bytes "
        "[%0], [%1], %2, [%3];"
        :: "r"(dst_smem), "l"(src), "r"(bytes), "r"(mbar) : "memory");
}

#define MBARRIER_INIT(mbar_smem_addr, count) \
    asm volatile("mbarrier.init.shared.b64 [%0], %1;" \
        :: "r"((uint32_t)(mbar_smem_addr)), "r"((uint32_t)(count)) : "memory")

#define MBARRIER_ARRIVE(mbar_smem_addr) \
    asm volatile("mbarrier.arrive.shared.b64 _, [%0];" \
        :: "r"((uint32_t)(mbar_smem_addr)) : "memory")

#define MBARRIER_EXPECT_TX(mbar_smem_addr, tx_bytes) \
    asm volatile("mbarrier.arrive.expect_tx.shared.b64 _, [%0], %1;" \
        :: "r"((uint32_t)(mbar_smem_addr)), "r"((uint32_t)(tx_bytes)) : "memory")

#define FENCE_PROXY_ASYNC_SHARED_CTA() \
    asm volatile("fence.proxy.async.shared::cta;" ::: "memory")

#define MBARRIER_WAIT_PARITY(mbar_smem_addr, phase_parity) do { \
    uint32_t _mbar = (uint32_t)(mbar_smem_addr); \
    uint32_t _parity = (uint32_t)(phase_parity); \
    uint32_t _done; \
    asm volatile( \
        "{\n\t.reg .pred p;\n\t" \
        "mbarrier.try_wait.parity.acquire.cta.shared::cta.b64 p, [%1], %2;\n\t" \
        "selp.b32 %0, 1, 0, p;\n\t}" \
        : "=r"(_done) : "r"(_mbar), "r"(_parity) : "memory"); \
    if (!_done) { \
        asm volatile( \
            "{\n\t.reg .pred P1;\n\t" \
            "WAIT_LOOP_%=:\n\t" \
            "mbarrier.try_wait.parity.acquire.cta.shared::cta.b64 P1, [%0], %1, 0x989680;\n\t" \
            "@P1 bra.uni WAIT_DONE_%=;\n\t" \
            "bra.uni WAIT_LOOP_%=;\n\t" \
            "WAIT_DONE_%=:\n\t}" \
            :: "r"(_mbar), "r"(_parity) : "memory"); \
    } \
} while(0)

__device__ __forceinline__ float gelu_exact(float x) {
    return 0.5f * x * (1.0f + erff(x * 0.70710678118654752f));
}

__device__ __forceinline__ uint32_t smem_to_u32(const void* smem_ptr) {
    uint32_t addr;
    asm("{ .reg .u64 tmp; cvta.to.shared.u64 tmp, %1; cvt.u32.u64 %0, tmp; }"
        : "=r"(addr) : "l"(smem_ptr));
    return addr;
}

// packed-tile index: (row r, col c) -> half offset; TK = K/64 blocks
__device__ __forceinline__ long long packIdx(int r, int c, int TK) {
    return ((long long)((r >> 7) * TK + (c >> 6)) * 128 + (r & 127)) * 72 + (c & 63);
}

// ---------------------------------------------------------------------------
// Fused prologue: all fp32->fp16 conversions in ONE kernel.
// ---------------------------------------------------------------------------
__device__ __forceinline__ void transpose_body(const float* __restrict__ in,
                                               __half* __restrict__ out,
                                               int K, int N, int k0, int n0,
                                               int tx, int ty, float (*t)[33]) {
#pragma unroll
    for (int i = 0; i < 32; i += 8)
        t[ty + i][tx] = in[(long long)(k0 + ty + i) * N + n0 + tx];
    __syncthreads();
    const int TK = K >> 6;
#pragma unroll
    for (int i = 0; i < 32; i += 8)
        out[packIdx(n0 + ty + i, k0 + tx, TK)] = __float2half_rn(t[tx][ty + i]);
}

__global__ void __launch_bounds__(256)
prologue_kernel(const float* __restrict__ x,
                const float* __restrict__ Wqkv,
                const float* __restrict__ Wproj,
                const float* __restrict__ W1,
                const float* __restrict__ W2,
                __half* __restrict__ XH,
                __half* __restrict__ WQKVH,
                __half* __restrict__ WPROJH,
                __half* __restrict__ W1H,
                __half* __restrict__ W2H)
{
    __shared__ float t[32][33];
    const int b = blockIdx.x;
    const int tid = threadIdx.x;
    const int tx = tid & 31, ty = tid >> 5;

    if (b < 8192) {
        const int i = b * 256 + tid;
        float4 v = *(const float4*)&x[(long long)i * 4];
        const int row = (i * 4) >> 10, col = (i * 4) & 1023;
        __half* o = XH + packIdx(row, col, 16);
        *(__half2*)o       = __floats2half2_rn(v.x, v.y);
        *(__half2*)(o + 2) = __floats2half2_rn(v.z, v.w);
    } else if (b < 11264) {
        const int bb = b - 8192;
        const int eb = bb % 6, kb = (bb / 6) % 32, h = bb / 192;
        const int k0 = kb * 32, e0 = eb * 32;
        const float* inh = Wqkv + (long long)h * 1024 * 192;
#pragma unroll
        for (int i = 0; i < 32; i += 8)
            t[ty + i][tx] = inh[(long long)(k0 + ty + i) * 192 + e0 + tx];
        __syncthreads();
#pragma unroll
        for (int i = 0; i < 32; i += 8)
            WQKVH[packIdx(h * 192 + e0 + ty + i, k0 + tx, 16)] =
                __float2half_rn(t[tx][ty + i]);
    } else if (b < 12288) {
        const int bb = b - 11264;
        transpose_body(Wproj, WPROJH, 1024, 1024,
                       (bb / 32) * 32, (bb % 32) * 32, tx, ty, t);
    } else if (b < 16384) {
        const int bb = b - 12288;
        transpose_body(W1, W1H, 1024, 4096,
                       (bb / 128) * 32, (bb % 128) * 32, tx, ty, t);
    } else {
        const int bb = b - 16384;
        transpose_body(W2, W2H, 4096, 1024,
                       (bb / 32) * 32, (bb % 32) * 32, tx, ty, t);
    }
}

// ---------------------------------------------------------------------------
// fp16 GEMM, bulk-TMA 2-stage producer/consumer pipeline.
// 512 threads, 16 warps (4x4), warp tile 32x32 -> 32 regs of accumulator,
// 8 warps/SMSP at 2 CTAs/SM for latency hiding.
// mode 0: Cf = acc + bias (flat); mode 1: Ch = half(gelu(acc+bias)) packed;
// mode 2: QKV half scatter (flat).
// ---------------------------------------------------------------------------
#define HB_TILE 18432
#define HB_STAGE 36864
#define HB_SMEM_BYTES (2 * HB_STAGE)    // 73728

__global__ void __launch_bounds__(512, 2)
hgemm_kernel(const __half* __restrict__ A,
             const __half* __restrict__ Bt,
             const float* __restrict__ bias,
             float* __restrict__ Cf,
             __half* __restrict__ Ch,
             int N, int K, int mode,
             __half* __restrict__ Qo, __half* __restrict__ Ko, __half* __restrict__ Vo)
{
    extern __shared__ char smem[];
    __shared__ __align__(8) uint64_t mbar_s[4];   // full0, full1, empty0, empty1

    const uint32_t su  = smem_to_u32(smem);
    const uint32_t mbF = smem_to_u32(&mbar_s[0]);
    const uint32_t mbE = mbF + 16;

    const int tid  = threadIdx.x;
    const int warp = tid >> 5, lane = tid & 31;
    const int wm = warp >> 2, wn = warp & 3;
    const int g = lane >> 2, tg = lane & 3;
    const int m0 = blockIdx.y * 128, n0 = blockIdx.x * 128;
    const int TK = K >> 6;

    const __half* Abase = A + (long long)blockIdx.y * TK * 9216;
    const __half* Bbase = Bt + (long long)blockIdx.x * TK * 9216;

    if (tid == 0) {
        MBARRIER_INIT(mbF, 1);
        MBARRIER_INIT(mbF + 8, 1);
        MBARRIER_INIT(mbE, 16);
        MBARRIER_INIT(mbE + 8, 16);
        FENCE_PROXY_ASYNC_SHARED_CTA();
    }
    __syncthreads();

    // ldmatrix per-thread byte offsets within a stage (144B row stride)
    uint32_t a_lm[2], b_lm4[2];
#pragma unroll
    for (int mt = 0; mt < 2; mt++)
        a_lm[mt] = (uint32_t)((wm * 32 + mt * 16 + (lane & 15)) * 144
                              + (lane >> 4) * 16);
    // merged B x4: pair p covers nt=2p,2p+1
#pragma unroll
    for (int p = 0; p < 2; p++)
        b_lm4[p] = (uint32_t)((wn * 32 + p * 16 + (lane >> 4) * 8 + (lane & 7)) * 144
                              + ((lane >> 3) & 1) * 16) + HB_TILE;

    float acc[2][4][4];
#pragma unroll
    for (int i = 0; i < 2; i++)
#pragma unroll
        for (int j = 0; j < 4; j++)
#pragma unroll
            for (int r = 0; r < 4; r++) acc[i][j][r] = 0.0f;

    // issue tiles 0 and 1
    if (tid == 0) {
        MBARRIER_EXPECT_TX(mbF, 2 * HB_TILE);
        cp_bulk(su, Abase, HB_TILE, mbF);
        cp_bulk(su + HB_TILE, Bbase, HB_TILE, mbF);
        if (TK > 1) {
            MBARRIER_EXPECT_TX(mbF + 8, 2 * HB_TILE);
            cp_bulk(su + HB_STAGE, Abase + 9216, HB_TILE, mbF + 8);
            cp_bulk(su + HB_STAGE + HB_TILE, Bbase + 9216, HB_TILE, mbF + 8);
        }
    }

    int phF0 = 0, phF1 = 0, phE0 = 0, phE1 = 0;
    for (int i = 0; i < TK; i++) {
        const int s = i & 1;
        if (s == 0) { MBARRIER_WAIT_PARITY(mbF, phF0);     phF0 ^= 1; }
        else        { MBARRIER_WAIT_PARITY(mbF + 8, phF1); phF1 ^= 1; }

        const uint32_t sb = su + s * HB_STAGE;
#pragma unroll
        for (int kc = 0; kc < 4; kc++) {
            uint32_t af[2][4];
#pragma unroll
            for (int mt = 0; mt < 2; mt++)
                ldm_x4(af[mt], sb + a_lm[mt] + kc * 32);
#pragma unroll
            for (int p = 0; p < 2; p++) {
                uint32_t bf[4];   // nt=2p (regs 0..1), nt=2p+1 (regs 2..3)
                ldm_x4(bf, sb + b_lm4[p] + kc * 32);
#pragma unroll
                for (int mt = 0; mt < 2; mt++) {
                    mma_f16(acc[mt][2 * p],     af[mt], &bf[0]);
                    mma_f16(acc[mt][2 * p + 1], af[mt], &bf[2]);
                }
            }
        }

        // signal this warp is done with stage s
        __syncwarp();
        if (lane == 0) MBARRIER_ARRIVE(mbE + s * 8);

        // producer: refill stage s with tile i+2 once all warps are done
        if (tid == 0 && i + 2 < TK) {
            if (s == 0) { MBARRIER_WAIT_PARITY(mbE, phE0);     phE0 ^= 1; }
            else        { MBARRIER_WAIT_PARITY(mbE + 8, phE1); phE1 ^= 1; }
            const uint32_t mb = mbF + s * 8;
            MBARRIER_EXPECT_TX(mb, 2 * HB_TILE);
            cp_bulk(su + s * HB_STAGE, Abase + (long long)(i + 2) * 9216, HB_TILE, mb);
            cp_bulk(su + s * HB_STAGE + HB_TILE, Bbase + (long long)(i + 2) * 9216, HB_TILE, mb);
        }
    }

    // epilogue
#pragma unroll
    for (int mt = 0; mt < 2; mt++) {
#pragma unroll
        for (int nt = 0; nt < 4; nt++) {
            const int row = m0 + wm * 32 + mt * 16 + g;
            const int col = n0 + wn * 32 + nt * 8 + 2 * tg;
            if (mode == 2) {
                const int head = col / 192;
                const int e = col % 192;
                __half* dst = (e < 64) ? Qo : (e < 128) ? Ko : Vo;
                const int eo = e & 63;
                const int bb = row >> 11, sc = row & 2047;
                const long long base = (((long long)bb * H_ + head) * S_ + sc) * DH_ + eo;
                *(__half2*)&dst[base] =
                    __floats2half2_rn(acc[mt][nt][0], acc[mt][nt][1]);
                *(__half2*)&dst[base + 8LL * DH_] =
                    __floats2half2_rn(acc[mt][nt][2], acc[mt][nt][3]);
            } else {
                const float b0 = bias[col], b1 = bias[col + 1];
                float v0 = acc[mt][nt][0] + b0;
                float v1 = acc[mt][nt][1] + b1;
                float v2 = acc[mt][nt][2] + b0;
                float v3 = acc[mt][nt][3] + b1;
                if (mode == 1) {
                    v0 = gelu_exact(v0); v1 = gelu_exact(v1);
                    v2 = gelu_exact(v2); v3 = gelu_exact(v3);
                    const int TKo = N >> 6;
                    *(__half2*)&Ch[packIdx(row, col, TKo)] = __floats2half2_rn(v0, v1);
                    *(__half2*)&Ch[packIdx(row + 8, col, TKo)] = __floats2half2_rn(v2, v3);
                } else {
                    *(float2*)&Cf[(long long)row * N + col] = make_float2(v0, v1);
                    *(float2*)&Cf[(long long)(row + 8) * N + col] = make_float2(v2, v3);
                }
            }
        }
    }
}

// ---------------------------------------------------------------------------
// Causal flash attention, fp16 MMA + merged ldmatrix.x4 (R15-proven, untouched).
// ---------------------------------------------------------------------------
#define FA_QB (128 * 144)
#define FA_KB (64 * 144)
#define FA_VB (64 * 144)
#define FA_PWB 2304
#define FA_SMEM_BYTES (FA_QB + FA_KB + FA_VB + 8 * FA_PWB)   // 55296

__global__ void __launch_bounds__(256)
flash_f16_kernel(const __half* __restrict__ Q,
                 const __half* __restrict__ K,
                 const __half* __restrict__ V,
                 __half* __restrict__ O)
{
    extern __shared__ char sm[];
    const int tid = threadIdx.x;
    const int warp = tid >> 5, lane = tid & 31;
    const int g = lane >> 2, tg = lane & 3;
    const int i0 = (gridDim.x - 1 - blockIdx.x) * 128;
    const int bh = blockIdx.y;

    const __half* Qg = Q + (long long)bh * S_ * DH_;
    const __half* Kg = K + (long long)bh * S_ * DH_;
    const __half* Vg = V + (long long)bh * S_ * DH_;

    const uint32_t su = smem_to_u32(sm);
    const uint32_t ku = su + FA_QB;
    const uint32_t vu = ku + FA_KB;
    const uint32_t pu = vu + FA_VB + warp * FA_PWB;
    char* pw = sm + FA_QB + FA_KB + FA_VB + warp * FA_PWB;

    const uint32_t qa_off = su + (uint32_t)((warp * 16 + (lane & 15)) * 144 + (lane >> 4) * 16);
    const uint32_t kb4_off = ku + (uint32_t)((lane & 7) * 144 + (lane >> 4) * 1152
                                             + ((lane >> 3) & 1) * 16);
    const uint32_t va4_off = vu + (uint32_t)((((lane >> 3) & 1) * 8 + (lane & 7)) * 144
                                             + (lane >> 4) * 16);
    const uint32_t pa_off = pu + (uint32_t)((lane & 15) * 144 + (lane >> 4) * 16);

#pragma unroll
    for (int i = 0; i < 4; i++) {
        int ch = tid + i * 256;
        int row = ch >> 3, c8 = (ch & 7) * 8;
        *(uint4*)(sm + row * 144 + c8 * 2) =
            *(const uint4*)&Qg[(long long)(i0 + row) * DH_ + c8];
    }

    float oacc[8][4];
#pragma unroll
    for (int nt = 0; nt < 8; nt++)
#pragma unroll
        for (int r = 0; r < 4; r++) oacc[nt][r] = 0.0f;

    float m0 = -1e30f, m1 = -1e30f, l0 = 0.0f, l1 = 0.0f;
    const int wrow0 = i0 + warp * 16;
    const int jtmax = (i0 + 127) >> 6;

    for (int jt = 0; jt <= jtmax; jt++) {
        const int j0 = jt << 6;
        __syncthreads();
#pragma unroll
        for (int i = 0; i < 2; i++) {
            int ch = tid + i * 256;
            int row = ch >> 3, c8 = (ch & 7) * 8;
            *(uint4*)(sm + FA_QB + row * 144 + c8 * 2) =
                *(const uint4*)&Kg[(long long)(j0 + row) * DH_ + c8];
            *(uint4*)(sm + FA_QB + FA_KB + row * 144 + c8 * 2) =
                *(const uint4*)&Vg[(long long)(j0 + row) * DH_ + c8];
        }
        __syncthreads();

        if (j0 > wrow0 + 15) continue;

        float sacc[8][4];
#pragma unroll
        for (int nt = 0; nt < 8; nt++)
#pragma unroll
            for (int r = 0; r < 4; r++) sacc[nt][r] = 0.0f;

#pragma unroll
        for (int kc = 0; kc < 4; kc++) {
            uint32_t aq[4];
            ldm_x4(aq, qa_off + kc * 32);
#pragma unroll
            for (int p = 0; p < 4; p++) {
                uint32_t bk[4];
                ldm_x4(bk, kb4_off + p * 2304 + kc * 32);
                mma_f16(sacc[2 * p],     aq, &bk[0]);
                mma_f16(sacc[2 * p + 1], aq, &bk[2]);
            }
        }

        const int row0 = wrow0 + g, row1 = wrow0 + 8 + g;
        const bool diag = (j0 + 63 > wrow0);
#pragma unroll
        for (int nt = 0; nt < 8; nt++) {
            sacc[nt][0] *= 0.125f; sacc[nt][1] *= 0.125f;
            sacc[nt][2] *= 0.125f; sacc[nt][3] *= 0.125f;
            if (diag) {
                const int c0 = j0 + nt * 8 + 2 * tg;
                if (c0 > row0)     sacc[nt][0] = -1e30f;
                if (c0 + 1 > row0) sacc[nt][1] = -1e30f;
                if (c0 > row1)     sacc[nt][2] = -1e30f;
                if (c0 + 1 > row1) sacc[nt][3] = -1e30f;
            }
        }

        float rm0 = -1e30f, rm1 = -1e30f;
#pragma unroll
        for (int nt = 0; nt < 8; nt++) {
            rm0 = fmaxf(rm0, fmaxf(sacc[nt][0], sacc[nt][1]));
            rm1 = fmaxf(rm1, fmaxf(sacc[nt][2], sacc[nt][3]));
        }
        rm0 = fmaxf(rm0, __shfl_xor_sync(0xffffffffu, rm0, 1));
        rm0 = fmaxf(rm0, __shfl_xor_sync(0xffffffffu, rm0, 2));
        rm1 = fmaxf(rm1, __shfl_xor_sync(0xffffffffu, rm1, 1));
        rm1 = fmaxf(rm1, __shfl_xor_sync(0xffffffffu, rm1, 2));

        const float mn0 = fmaxf(m0, rm0), mn1 = fmaxf(m1, rm1);
        const float cr0 = __expf(m0 - mn0), cr1 = __expf(m1 - mn1);
        float rs0 = 0.0f, rs1 = 0.0f;

        __syncwarp();
#pragma unroll
        for (int nt = 0; nt < 8; nt++) {
            __half2 ha = __floats2half2_rn(__expf(sacc[nt][0] - mn0),
                                           __expf(sacc[nt][1] - mn0));
            __half2 hb = __floats2half2_rn(__expf(sacc[nt][2] - mn1),
                                           __expf(sacc[nt][3] - mn1));
            rs0 += __low2float(ha) + __high2float(ha);
            rs1 += __low2float(hb) + __high2float(hb);
            *(__half2*)(pw + g * 144 + (nt * 8 + 2 * tg) * 2) = ha;
            *(__half2*)(pw + (g + 8) * 144 + (nt * 8 + 2 * tg) * 2) = hb;
        }
        __syncwarp();

        rs0 += __shfl_xor_sync(0xffffffffu, rs0, 1);
        rs0 += __shfl_xor_sync(0xffffffffu, rs0, 2);
        rs1 += __shfl_xor_sync(0xffffffffu, rs1, 1);
        rs1 += __shfl_xor_sync(0xffffffffu, rs1, 2);

        l0 = l0 * cr0 + rs0;
        l1 = l1 * cr1 + rs1;
        m0 = mn0; m1 = mn1;

#pragma unroll
        for (int nt = 0; nt < 8; nt++) {
            oacc[nt][0] *= cr0; oacc[nt][1] *= cr0;
            oacc[nt][2] *= cr1; oacc[nt][3] *= cr1;
        }

#pragma unroll
        for (int kc = 0; kc < 4; kc++) {
            uint32_t ap[4];
            ldm_x4(ap, pa_off + kc * 32);
#pragma unroll
            for (int p = 0; p < 4; p++) {
                uint32_t bv[4];
                ldm_x4t(bv, va4_off + kc * 2304 + p * 32);
                mma_f16(oacc[2 * p],     ap, &bv[0]);
                mma_f16(oacc[2 * p + 1], ap, &bv[2]);
            }
        }
    }

    // epilogue: packed layout for proj GEMM (K=1024 -> TK=16)
    const int b = bh >> 4, h = bh & 15;
    const float inv0 = 1.0f / l0, inv1 = 1.0f / l1;
    const int row0 = wrow0 + g, row1 = wrow0 + 8 + g;
#pragma unroll
    for (int nt = 0; nt < 8; nt++) {
        const int col = h * 64 + nt * 8 + 2 * tg;
        *(__half2*)&O[packIdx(b * S_ + row0, col, 16)] =
            __floats2half2_rn(oacc[nt][0] * inv0, oacc[nt][1] * inv0);
        *(__half2*)&O[packIdx(b * S_ + row1, col, 16)] =
            __floats2half2_rn(oacc[nt][2] * inv1, oacc[nt][3] * inv1);
    }
}

// ---------------------------------------------------------------------------
// Fused residual + LayerNorm. Optional packed fp16 second copy (K=1024).
// ---------------------------------------------------------------------------
__global__ void ln_kernel(const float* __restrict__ A,
                          const float* __restrict__ R,
                          const float* __restrict__ G,
                          const float* __restrict__ Be,
                          float* __restrict__ Out,
                          __half* __restrict__ OutH)
{
    const int row = blockIdx.x;
    const int tid = threadIdx.x;
    const long long base = (long long)row * D_;

    float4 va = *(const float4*)&A[base + tid * 4];
    float4 vb = *(const float4*)&R[base + tid * 4];
    float4 v = make_float4(va.x + vb.x, va.y + vb.y, va.z + vb.z, va.w + vb.w);

    float s = v.x + v.y + v.z + v.w;
    float ss = v.x * v.x + v.y * v.y + v.z * v.z + v.w * v.w;

    __shared__ float rs_[8], rss_[8];
#pragma unroll
    for (int off = 16; off >= 1; off >>= 1) {
        s += __shfl_xor_sync(0xffffffffu, s, off);
        ss += __shfl_xor_sync(0xffffffffu, ss, off);
    }
    int warp = tid >> 5, lane = tid & 31;
    if (lane == 0) { rs_[warp] = s; rss_[warp] = ss; }
    __syncthreads();
    if (warp == 0) {
        s = (lane < 8) ? rs_[lane] : 0.0f;
        ss = (lane < 8) ? rss_[lane] : 0.0f;
#pragma unroll
        for (int off = 4; off >= 1; off >>= 1) {
            s += __shfl_xor_sync(0xffffffffu, s, off);
            ss += __shfl_xor_sync(0xffffffffu, ss, off);
        }
        if (lane == 0) { rs_[0] = s; rss_[0] = ss; }
    }
    __syncthreads();
    s = rs_[0]; ss = rss_[0];

    const float mu = s * (1.0f / 1024.0f);
    const float var = ss * (1.0f / 1024.0f) - mu * mu;
    const float rstd = rsqrtf(var + 1e-5f);

    float4 g4 = *(const float4*)&G[tid * 4];
    float4 b4 = *(const float4*)&Be[tid * 4];
    float4 ov;
    ov.x = (v.x - mu) * rstd * g4.x + b4.x;
    ov.y = (v.y - mu) * rstd * g4.y + b4.y;
    ov.z = (v.z - mu) * rstd * g4.z + b4.z;
    ov.w = (v.w - mu) * rstd * g4.w + b4.w;
    *(float4*)&Out[base + tid * 4] = ov;
    if (OutH) {
        __half* o = OutH + packIdx(row, tid * 4, 16);
        *(__half2*)o       = __floats2half2_rn(ov.x, ov.y);
        *(__half2*)(o + 2) = __floats2half2_rn(ov.z, ov.w);
    }
}

// ---------------------------------------------------------------------------
extern "C" void kernel_launch(void* const* d_in, const int* in_sizes, int n_in,
                              void* d_out, int out_size)
{
    (void)in_sizes; (void)n_in; (void)out_size;
    const float* x     = (const float*)d_in[0];
    const float* Wqkv  = (const float*)d_in[1];
    const float* Wproj = (const float*)d_in[2];
    const float* bproj = (const float*)d_in[3];
    const float* ln1g  = (const float*)d_in[4];
    const float* ln1b  = (const float*)d_in[5];
    const float* ln2g  = (const float*)d_in[6];
    const float* ln2b  = (const float*)d_in[7];
    const float* W1    = (const float*)d_in[8];
    const float* b1    = (const float*)d_in[9];
    const float* W2    = (const float*)d_in[10];
    const float* b2    = (const float*)d_in[11];
    float* out = (float*)d_out;

    float* scratch = nullptr;
    cudaGetSymbolAddress((void**)&scratch, g_scratch);

    float* PROJ = scratch + OFF_PROJ;
    float* LN1  = scratch + OFF_LN1;
    float* MLP  = scratch + OFF_MLP;

    __half* hbase  = (__half*)(scratch + FLOAT_END);
    __half* QH     = hbase + HOFF_Q;
    __half* KH     = hbase + HOFF_K;
    __half* VH     = hbase + HOFF_V;
    __half* ATTH   = hbase + HOFF_ATT;
    __half* XH     = hbase + HOFF_X;
    __half* LN1H   = hbase + HOFF_LN1;
    __half* WQKVH  = hbase + HOFF_WQKV;
    __half* WPROJH = hbase + HOFF_WPROJ;
    __half* W1H    = hbase + HOFF_W1;
    __half* W2H    = hbase + HOFF_W2;
    __half* FFHH   = hbase + HOFF_FFH;

    cudaFuncSetAttribute(hgemm_kernel,
                         cudaFuncAttributeMaxDynamicSharedMemorySize, HB_SMEM_BYTES);
    cudaFuncSetAttribute(flash_f16_kernel,
                         cudaFuncAttributeMaxDynamicSharedMemorySize, FA_SMEM_BYTES);

    // 0) fused fp16 conversion prologue (single launch)
    prologue_kernel<<<20480, 256>>>(x, Wqkv, Wproj, W1, W2,
                                    XH, WQKVH, WPROJH, W1H, W2H);

    // 1) QKV projection -> fp16 Q/K/V (flat)
    hgemm_kernel<<<dim3(24, 64), 512, HB_SMEM_BYTES>>>(
        XH, WQKVH, nullptr, nullptr, nullptr, 3072, 1024, 2, QH, KH, VH);

    // 2) causal flash attention -> fp16 ATT (packed)
    flash_f16_kernel<<<dim3(16, 64), 256, FA_SMEM_BYTES>>>(QH, KH, VH, ATTH);

    // 3) output projection + bias -> fp32 flat
    hgemm_kernel<<<dim3(8, 64), 512, HB_SMEM_BYTES>>>(
        ATTH, WPROJH, bproj, PROJ, nullptr, 1024, 1024, 0, nullptr, nullptr, nullptr);

    // 4) residual + LN1 (fp32 + packed fp16 copy)
    ln_kernel<<<8192, 256>>>(x, PROJ, ln1g, ln1b, LN1, LN1H);

    // 5) MLP up + bias + GELU -> fp16 packed
    hgemm_kernel<<<dim3(32, 64), 512, HB_SMEM_BYTES>>>(
        LN1H, W1H, b1, nullptr, FFHH, 4096, 1024, 1, nullptr, nullptr, nullptr);

    // 6) MLP down + bias -> fp32 flat
    hgemm_kernel<<<dim3(8, 64), 512, HB_SMEM_BYTES>>>(
        FFHH, W2H, b2, MLP, nullptr, 1024, 4096, 0, nullptr, nullptr, nullptr);

    // 7) residual + LN2 -> output
    ln_kernel<<<8192, 256>>>(LN1, MLP, ln2g, ln2b, out, nullptr);
}

// round 17
// speedup vs baseline: 1.0156x; 1.0156x over previous
#include <cuda_runtime.h>
#include <cuda_fp16.h>
#include <math.h>
#include <cstdint>

// Problem constants
#define B_ 4
#define S_ 2048
#define D_ 1024
#define H_ 16
#define DH_ 64
#define DFF_ 4096

// Scratch layout
// float region (floats)
#define OFF_PROJ  0LL
#define OFF_LN1   8388608LL
#define OFF_MLP   16777216LL
#define FLOAT_END 25165824LL
// half region (halves, from hbase). Packed operands use tile layout:
// [rblk][kblk][128 rows][72 halves] (64 data + 8 pad), tile = 9216 halves.
#define HOFF_Q     0LL
#define HOFF_K     8388608LL
#define HOFF_V     16777216LL
#define HOFF_ATT   25165824LL
#define HOFF_X     34603008LL
#define HOFF_LN1   44040192LL
#define HOFF_WQKV  53477376LL
#define HOFF_WPROJ 57016320LL
#define HOFF_W1    58195968LL
#define HOFF_W2    62914560LL
#define HOFF_FFH   67633152LL
#define HALF_END   105381888LL
#define SCRATCH_TOTAL (FLOAT_END + HALF_END / 2)   // 77856768 floats

__device__ __align__(256) float g_scratch[SCRATCH_TOTAL];

// ---------------------------------------------------------------------------
// helpers
// ---------------------------------------------------------------------------
__device__ __forceinline__ void mma_f16(float c[4], const uint32_t a[4], const uint32_t b[2]) {
    asm volatile(
        "mma.sync.aligned.m16n8k16.row.col.f32.f16.f16.f32 "
        "{%0,%1,%2,%3}, {%4,%5,%6,%7}, {%8,%9}, {%0,%1,%2,%3};"
        : "+f"(c[0]), "+f"(c[1]), "+f"(c[2]), "+f"(c[3])
        : "r"(a[0]), "r"(a[1]), "r"(a[2]), "r"(a[3]),
          "r"(b[0]), "r"(b[1]));
}

__device__ __forceinline__ void ldm_x4(uint32_t r[4], uint32_t addr) {
    asm volatile("ldmatrix.sync.aligned.m8n8.x4.shared.b16 {%0,%1,%2,%3}, [%4];"
        : "=r"(r[0]), "=r"(r[1]), "=r"(r[2]), "=r"(r[3]) : "r"(addr));
}
__device__ __forceinline__ void ldm_x4t(uint32_t r[4], uint32_t addr) {
    asm volatile("ldmatrix.sync.aligned.m8n8.x4.trans.shared.b16 {%0,%1,%2,%3}, [%4];"
        : "=r"(r[0]), "=r"(r[1]), "=r"(r[2]), "=r"(r[3]) : "r"(addr));
}

// 1D bulk async copy global->shared with mbarrier completion (sm_90 base)
__device__ __forceinline__ void cp_bulk(uint32_t dst_smem, const void* src,
                                        uint32_t bytes, uint32_t mbar) {
    asm volatile(
        "cp.async.bulk.shared::cluster.global.mbarrier::complete_tx::bytes "
        "[%0], [%1], %2, [%3];"
        :: "r"(dst_smem), "l"(src), "r"(bytes), "r"(mbar) : "memory");
}

#define MBARRIER_INIT(mbar_smem_addr, count) \
    asm volatile("mbarrier.init.shared.b64 [%0], %1;" \
        :: "r"((uint32_t)(mbar_smem_addr)), "r"((uint32_t)(count)) : "memory")

#define MBARRIER_ARRIVE(mbar_smem_addr) \
    asm volatile("mbarrier.arrive.shared.b64 _, [%0];" \
        :: "r"((uint32_t)(mbar_smem_addr)) : "memory")

#define MBARRIER_EXPECT_TX(mbar_smem_addr, tx_bytes) \
    asm volatile("mbarrier.arrive.expect_tx.shared.b64 _, [%0], %1;" \
        :: "r"((uint32_t)(mbar_smem_addr)), "r"((uint32_t)(tx_bytes)) : "memory")

#define FENCE_PROXY_ASYNC_SHARED_CTA() \
    asm volatile("fence.proxy.async.shared::cta;" ::: "memory")

#define MBARRIER_WAIT_PARITY(mbar_smem_addr, phase_parity) do { \
    uint32_t _mbar = (uint32_t)(mbar_smem_addr); \
    uint32_t _parity = (uint32_t)(phase_parity); \
    uint32_t _done; \
    asm volatile( \
        "{\n\t.reg .pred p;\n\t" \
        "mbarrier.try_wait.parity.acquire.cta.shared::cta.b64 p, [%1], %2;\n\t" \
        "selp.b32 %0, 1, 0, p;\n\t}" \
        : "=r"(_done) : "r"(_mbar), "r"(_parity) : "memory"); \
    if (!_done) { \
        asm volatile( \
            "{\n\t.reg .pred P1;\n\t" \
            "WAIT_LOOP_%=:\n\t" \
            "mbarrier.try_wait.parity.acquire.cta.shared::cta.b64 P1, [%0], %1, 0x989680;\n\t" \
            "@P1 bra.uni WAIT_DONE_%=;\n\t" \
            "bra.uni WAIT_LOOP_%=;\n\t" \
            "WAIT_DONE_%=:\n\t}" \
            :: "r"(_mbar), "r"(_parity) : "memory"); \
    } \
} while(0)

__device__ __forceinline__ float gelu_exact(float x) {
    return 0.5f * x * (1.0f + erff(x * 0.70710678118654752f));
}

__device__ __forceinline__ uint32_t smem_to_u32(const void* smem_ptr) {
    uint32_t addr;
    asm("{ .reg .u64 tmp; cvta.to.shared.u64 tmp, %1; cvt.u32.u64 %0, tmp; }"
        : "=r"(addr) : "l"(smem_ptr));
    return addr;
}

// packed-tile index: (row r, col c) -> half offset; TK = K/64 blocks
__device__ __forceinline__ long long packIdx(int r, int c, int TK) {
    return ((long long)((r >> 7) * TK + (c >> 6)) * 128 + (r & 127)) * 72 + (c & 63);
}

// ---------------------------------------------------------------------------
// Fused prologue: all fp32->fp16 conversions in ONE kernel.
// ---------------------------------------------------------------------------
__device__ __forceinline__ void transpose_body(const float* __restrict__ in,
                                               __half* __restrict__ out,
                                               int K, int N, int k0, int n0,
                                               int tx, int ty, float (*t)[33]) {
#pragma unroll
    for (int i = 0; i < 32; i += 8)
        t[ty + i][tx] = in[(long long)(k0 + ty + i) * N + n0 + tx];
    __syncthreads();
    const int TK = K >> 6;
#pragma unroll
    for (int i = 0; i < 32; i += 8)
        out[packIdx(n0 + ty + i, k0 + tx, TK)] = __float2half_rn(t[tx][ty + i]);
}

__global__ void __launch_bounds__(256)
prologue_kernel(const float* __restrict__ x,
                const float* __restrict__ Wqkv,
                const float* __restrict__ Wproj,
                const float* __restrict__ W1,
                const float* __restrict__ W2,
                __half* __restrict__ XH,
                __half* __restrict__ WQKVH,
                __half* __restrict__ WPROJH,
                __half* __restrict__ W1H,
                __half* __restrict__ W2H)
{
    __shared__ float t[32][33];
    const int b = blockIdx.x;
    const int tid = threadIdx.x;
    const int tx = tid & 31, ty = tid >> 5;

    if (b < 8192) {
        const int i = b * 256 + tid;
        float4 v = *(const float4*)&x[(long long)i * 4];
        const int row = (i * 4) >> 10, col = (i * 4) & 1023;
        __half* o = XH + packIdx(row, col, 16);
        *(__half2*)o       = __floats2half2_rn(v.x, v.y);
        *(__half2*)(o + 2) = __floats2half2_rn(v.z, v.w);
    } else if (b < 11264) {
        const int bb = b - 8192;
        const int eb = bb % 6, kb = (bb / 6) % 32, h = bb / 192;
        const int k0 = kb * 32, e0 = eb * 32;
        const float* inh = Wqkv + (long long)h * 1024 * 192;
#pragma unroll
        for (int i = 0; i < 32; i += 8)
            t[ty + i][tx] = inh[(long long)(k0 + ty + i) * 192 + e0 + tx];
        __syncthreads();
#pragma unroll
        for (int i = 0; i < 32; i += 8)
            WQKVH[packIdx(h * 192 + e0 + ty + i, k0 + tx, 16)] =
                __float2half_rn(t[tx][ty + i]);
    } else if (b < 12288) {
        const int bb = b - 11264;
        transpose_body(Wproj, WPROJH, 1024, 1024,
                       (bb / 32) * 32, (bb % 32) * 32, tx, ty, t);
    } else if (b < 16384) {
        const int bb = b - 12288;
        transpose_body(W1, W1H, 1024, 4096,
                       (bb / 128) * 32, (bb % 128) * 32, tx, ty, t);
    } else {
        const int bb = b - 16384;
        transpose_body(W2, W2H, 4096, 1024,
                       (bb / 32) * 32, (bb % 32) * 32, tx, ty, t);
    }
}

// ---------------------------------------------------------------------------
// fp16 GEMM (R15-proven): bulk-TMA 2-stage producer/consumer pipeline,
// 256 threads, 8 warps (2x4), warp tile 64x32, merged B ldmatrix.x4.
// mode 0: Cf = acc + bias (flat); mode 1: Ch = half(gelu(acc+bias)) packed;
// mode 2: QKV half scatter (flat).
// ---------------------------------------------------------------------------
#define HB_TILE 18432
#define HB_STAGE 36864
#define HB_SMEM_BYTES (2 * HB_STAGE)    // 73728

__global__ void __launch_bounds__(256, 2)
hgemm_kernel(const __half* __restrict__ A,
             const __half* __restrict__ Bt,
             const float* __restrict__ bias,
             float* __restrict__ Cf,
             __half* __restrict__ Ch,
             int N, int K, int mode,
             __half* __restrict__ Qo, __half* __restrict__ Ko, __half* __restrict__ Vo)
{
    extern __shared__ char smem[];
    __shared__ __align__(8) uint64_t mbar_s[4];   // full0, full1, empty0, empty1

    const uint32_t su  = smem_to_u32(smem);
    const uint32_t mbF = smem_to_u32(&mbar_s[0]);
    const uint32_t mbE = mbF + 16;

    const int tid  = threadIdx.x;
    const int warp = tid >> 5, lane = tid & 31;
    const int wm = warp >> 2, wn = warp & 3;
    const int g = lane >> 2, tg = lane & 3;
    const int m0 = blockIdx.y * 128, n0 = blockIdx.x * 128;
    const int TK = K >> 6;

    const __half* Abase = A + (long long)blockIdx.y * TK * 9216;
    const __half* Bbase = Bt + (long long)blockIdx.x * TK * 9216;

    if (tid == 0) {
        MBARRIER_INIT(mbF, 1);
        MBARRIER_INIT(mbF + 8, 1);
        MBARRIER_INIT(mbE, 8);
        MBARRIER_INIT(mbE + 8, 8);
        FENCE_PROXY_ASYNC_SHARED_CTA();
    }
    __syncthreads();

    // ldmatrix per-thread byte offsets within a stage (144B row stride)
    uint32_t a_lm[4], b_lm4[2];
#pragma unroll
    for (int mt = 0; mt < 4; mt++)
        a_lm[mt] = (uint32_t)((wm * 64 + mt * 16 + (lane & 15)) * 144
                              + (lane >> 4) * 16);
    // merged B x4: pair p covers nt=2p,2p+1
#pragma unroll
    for (int p = 0; p < 2; p++)
        b_lm4[p] = (uint32_t)((wn * 32 + p * 16 + (lane >> 4) * 8 + (lane & 7)) * 144
                              + ((lane >> 3) & 1) * 16) + HB_TILE;

    float acc[4][4][4];
#pragma unroll
    for (int i = 0; i < 4; i++)
#pragma unroll
        for (int j = 0; j < 4; j++)
#pragma unroll
            for (int r = 0; r < 4; r++) acc[i][j][r] = 0.0f;

    // issue tiles 0 and 1
    if (tid == 0) {
        MBARRIER_EXPECT_TX(mbF, 2 * HB_TILE);
        cp_bulk(su, Abase, HB_TILE, mbF);
        cp_bulk(su + HB_TILE, Bbase, HB_TILE, mbF);
        if (TK > 1) {
            MBARRIER_EXPECT_TX(mbF + 8, 2 * HB_TILE);
            cp_bulk(su + HB_STAGE, Abase + 9216, HB_TILE, mbF + 8);
            cp_bulk(su + HB_STAGE + HB_TILE, Bbase + 9216, HB_TILE, mbF + 8);
        }
    }

    int phF0 = 0, phF1 = 0, phE0 = 0, phE1 = 0;
    for (int i = 0; i < TK; i++) {
        const int s = i & 1;
        if (s == 0) { MBARRIER_WAIT_PARITY(mbF, phF0);     phF0 ^= 1; }
        else        { MBARRIER_WAIT_PARITY(mbF + 8, phF1); phF1 ^= 1; }

        const uint32_t sb = su + s * HB_STAGE;
#pragma unroll
        for (int kc = 0; kc < 4; kc++) {
            uint32_t af[4][4], bf[4][2];
#pragma unroll
            for (int mt = 0; mt < 4; mt++)
                ldm_x4(af[mt], sb + a_lm[mt] + kc * 32);
            ldm_x4(&bf[0][0], sb + b_lm4[0] + kc * 32);
            ldm_x4(&bf[2][0], sb + b_lm4[1] + kc * 32);
#pragma unroll
            for (int mt = 0; mt < 4; mt++)
#pragma unroll
                for (int nt = 0; nt < 4; nt++)
                    mma_f16(acc[mt][nt], af[mt], bf[nt]);
        }

        // signal this warp is done with stage s
        __syncwarp();
        if (lane == 0) MBARRIER_ARRIVE(mbE + s * 8);

        // producer: refill stage s with tile i+2 once all warps are done
        if (tid == 0 && i + 2 < TK) {
            if (s == 0) { MBARRIER_WAIT_PARITY(mbE, phE0);     phE0 ^= 1; }
            else        { MBARRIER_WAIT_PARITY(mbE + 8, phE1); phE1 ^= 1; }
            const uint32_t mb = mbF + s * 8;
            MBARRIER_EXPECT_TX(mb, 2 * HB_TILE);
            cp_bulk(su + s * HB_STAGE, Abase + (long long)(i + 2) * 9216, HB_TILE, mb);
            cp_bulk(su + s * HB_STAGE + HB_TILE, Bbase + (long long)(i + 2) * 9216, HB_TILE, mb);
        }
    }

    // epilogue
#pragma unroll
    for (int mt = 0; mt < 4; mt++) {
#pragma unroll
        for (int nt = 0; nt < 4; nt++) {
            const int row = m0 + wm * 64 + mt * 16 + g;
            const int col = n0 + wn * 32 + nt * 8 + 2 * tg;
            if (mode == 2) {
                const int head = col / 192;
                const int e = col % 192;
                __half* dst = (e < 64) ? Qo : (e < 128) ? Ko : Vo;
                const int eo = e & 63;
                const int bb = row >> 11, sc = row & 2047;
                const long long base = (((long long)bb * H_ + head) * S_ + sc) * DH_ + eo;
                *(__half2*)&dst[base] =
                    __floats2half2_rn(acc[mt][nt][0], acc[mt][nt][1]);
                *(__half2*)&dst[base + 8LL * DH_] =
                    __floats2half2_rn(acc[mt][nt][2], acc[mt][nt][3]);
            } else {
                const float b0 = bias[col], b1 = bias[col + 1];
                float v0 = acc[mt][nt][0] + b0;
                float v1 = acc[mt][nt][1] + b1;
                float v2 = acc[mt][nt][2] + b0;
                float v3 = acc[mt][nt][3] + b1;
                if (mode == 1) {
                    v0 = gelu_exact(v0); v1 = gelu_exact(v1);
                    v2 = gelu_exact(v2); v3 = gelu_exact(v3);
                    const int TKo = N >> 6;
                    *(__half2*)&Ch[packIdx(row, col, TKo)] = __floats2half2_rn(v0, v1);
                    *(__half2*)&Ch[packIdx(row + 8, col, TKo)] = __floats2half2_rn(v2, v3);
                } else {
                    *(float2*)&Cf[(long long)row * N + col] = make_float2(v0, v1);
                    *(float2*)&Cf[(long long)(row + 8) * N + col] = make_float2(v2, v3);
                }
            }
        }
    }
}

// ---------------------------------------------------------------------------
// Causal flash attention, fp16 MMA + merged ldmatrix.x4; Q fragments hoisted
// into registers once (Q invariant over the KV loop) — removes 4 x4-LDSM per
// tile per warp from the S loop.
// ---------------------------------------------------------------------------
#define FA_QB (128 * 144)
#define FA_KB (64 * 144)
#define FA_VB (64 * 144)
#define FA_PWB 2304
#define FA_SMEM_BYTES (FA_QB + FA_KB + FA_VB + 8 * FA_PWB)   // 55296

__global__ void __launch_bounds__(256)
flash_f16_kernel(const __half* __restrict__ Q,
                 const __half* __restrict__ K,
                 const __half* __restrict__ V,
                 __half* __restrict__ O)
{
    extern __shared__ char sm[];
    const int tid = threadIdx.x;
    const int warp = tid >> 5, lane = tid & 31;
    const int g = lane >> 2, tg = lane & 3;
    const int i0 = (gridDim.x - 1 - blockIdx.x) * 128;
    const int bh = blockIdx.y;

    const __half* Qg = Q + (long long)bh * S_ * DH_;
    const __half* Kg = K + (long long)bh * S_ * DH_;
    const __half* Vg = V + (long long)bh * S_ * DH_;

    const uint32_t su = smem_to_u32(sm);
    const uint32_t ku = su + FA_QB;
    const uint32_t vu = ku + FA_KB;
    const uint32_t pu = vu + FA_VB + warp * FA_PWB;
    char* pw = sm + FA_QB + FA_KB + FA_VB + warp * FA_PWB;

    const uint32_t qa_off = su + (uint32_t)((warp * 16 + (lane & 15)) * 144 + (lane >> 4) * 16);
    const uint32_t kb4_off = ku + (uint32_t)((lane & 7) * 144 + (lane >> 4) * 1152
                                             + ((lane >> 3) & 1) * 16);
    const uint32_t va4_off = vu + (uint32_t)((((lane >> 3) & 1) * 8 + (lane & 7)) * 144
                                             + (lane >> 4) * 16);
    const uint32_t pa_off = pu + (uint32_t)((lane & 15) * 144 + (lane >> 4) * 16);

#pragma unroll
    for (int i = 0; i < 4; i++) {
        int ch = tid + i * 256;
        int row = ch >> 3, c8 = (ch & 7) * 8;
        *(uint4*)(sm + row * 144 + c8 * 2) =
            *(const uint4*)&Qg[(long long)(i0 + row) * DH_ + c8];
    }
    __syncthreads();

    // hoist Q fragments (invariant across the KV loop)
    uint32_t qf[4][4];
#pragma unroll
    for (int kc = 0; kc < 4; kc++)
        ldm_x4(qf[kc], qa_off + kc * 32);

    float oacc[8][4];
#pragma unroll
    for (int nt = 0; nt < 8; nt++)
#pragma unroll
        for (int r = 0; r < 4; r++) oacc[nt][r] = 0.0f;

    float m0 = -1e30f, m1 = -1e30f, l0 = 0.0f, l1 = 0.0f;
    const int wrow0 = i0 + warp * 16;
    const int jtmax = (i0 + 127) >> 6;

    for (int jt = 0; jt <= jtmax; jt++) {
        const int j0 = jt << 6;
        __syncthreads();
#pragma unroll
        for (int i = 0; i < 2; i++) {
            int ch = tid + i * 256;
            int row = ch >> 3, c8 = (ch & 7) * 8;
            *(uint4*)(sm + FA_QB + row * 144 + c8 * 2) =
                *(const uint4*)&Kg[(long long)(j0 + row) * DH_ + c8];
            *(uint4*)(sm + FA_QB + FA_KB + row * 144 + c8 * 2) =
                *(const uint4*)&Vg[(long long)(j0 + row) * DH_ + c8];
        }
        __syncthreads();

        if (j0 > wrow0 + 15) continue;

        float sacc[8][4];
#pragma unroll
        for (int nt = 0; nt < 8; nt++)
#pragma unroll
            for (int r = 0; r < 4; r++) sacc[nt][r] = 0.0f;

#pragma unroll
        for (int kc = 0; kc < 4; kc++) {
#pragma unroll
            for (int p = 0; p < 4; p++) {
                uint32_t bk[4];
                ldm_x4(bk, kb4_off + p * 2304 + kc * 32);
                mma_f16(sacc[2 * p],     qf[kc], &bk[0]);
                mma_f16(sacc[2 * p + 1], qf[kc], &bk[2]);
            }
        }

        const int row0 = wrow0 + g, row1 = wrow0 + 8 + g;
        const bool diag = (j0 + 63 > wrow0);
#pragma unroll
        for (int nt = 0; nt < 8; nt++) {
            sacc[nt][0] *= 0.125f; sacc[nt][1] *= 0.125f;
            sacc[nt][2] *= 0.125f; sacc[nt][3] *= 0.125f;
            if (diag) {
                const int c0 = j0 + nt * 8 + 2 * tg;
                if (c0 > row0)     sacc[nt][0] = -1e30f;
                if (c0 + 1 > row0) sacc[nt][1] = -1e30f;
                if (c0 > row1)     sacc[nt][2] = -1e30f;
                if (c0 + 1 > row1) sacc[nt][3] = -1e30f;
            }
        }

        float rm0 = -1e30f, rm1 = -1e30f;
#pragma unroll
        for (int nt = 0; nt < 8; nt++) {
            rm0 = fmaxf(rm0, fmaxf(sacc[nt][0], sacc[nt][1]));
            rm1 = fmaxf(rm1, fmaxf(sacc[nt][2], sacc[nt][3]));
        }
        rm0 = fmaxf(rm0, __shfl_xor_sync(0xffffffffu, rm0, 1));
        rm0 = fmaxf(rm0, __shfl_xor_sync(0xffffffffu, rm0, 2));
        rm1 = fmaxf(rm1, __shfl_xor_sync(0xffffffffu, rm1, 1));
        rm1 = fmaxf(rm1, __shfl_xor_sync(0xffffffffu, rm1, 2));

        const float mn0 = fmaxf(m0, rm0), mn1 = fmaxf(m1, rm1);
        const float cr0 = __expf(m0 - mn0), cr1 = __expf(m1 - mn1);
        float rs0 = 0.0f, rs1 = 0.0f;

        __syncwarp();
#pragma unroll
        for (int nt = 0; nt < 8; nt++) {
            __half2 ha = __floats2half2_rn(__expf(sacc[nt][0] - mn0),
                                           __expf(sacc[nt][1] - mn0));
            __half2 hb = __floats2half2_rn(__expf(sacc[nt][2] - mn1),
                                           __expf(sacc[nt][3] - mn1));
            rs0 += __low2float(ha) + __high2float(ha);
            rs1 += __low2float(hb) + __high2float(hb);
            *(__half2*)(pw + g * 144 + (nt * 8 + 2 * tg) * 2) = ha;
            *(__half2*)(pw + (g + 8) * 144 + (nt * 8 + 2 * tg) * 2) = hb;
        }
        __syncwarp();

        rs0 += __shfl_xor_sync(0xffffffffu, rs0, 1);
        rs0 += __shfl_xor_sync(0xffffffffu, rs0, 2);
        rs1 += __shfl_xor_sync(0xffffffffu, rs1, 1);
        rs1 += __shfl_xor_sync(0xffffffffu, rs1, 2);

        l0 = l0 * cr0 + rs0;
        l1 = l1 * cr1 + rs1;
        m0 = mn0; m1 = mn1;

#pragma unroll
        for (int nt = 0; nt < 8; nt++) {
            oacc[nt][0] *= cr0; oacc[nt][1] *= cr0;
            oacc[nt][2] *= cr1; oacc[nt][3] *= cr1;
        }

#pragma unroll
        for (int kc = 0; kc < 4; kc++) {
            uint32_t ap[4];
            ldm_x4(ap, pa_off + kc * 32);
#pragma unroll
            for (int p = 0; p < 4; p++) {
                uint32_t bv[4];
                ldm_x4t(bv, va4_off + kc * 2304 + p * 32);
                mma_f16(oacc[2 * p],     ap, &bv[0]);
                mma_f16(oacc[2 * p + 1], ap, &bv[2]);
            }
        }
    }

    // epilogue: packed layout for proj GEMM (K=1024 -> TK=16)
    const int b = bh >> 4, h = bh & 15;
    const float inv0 = 1.0f / l0, inv1 = 1.0f / l1;
    const int row0 = wrow0 + g, row1 = wrow0 + 8 + g;
#pragma unroll
    for (int nt = 0; nt < 8; nt++) {
        const int col = h * 64 + nt * 8 + 2 * tg;
        *(__half2*)&O[packIdx(b * S_ + row0, col, 16)] =
            __floats2half2_rn(oacc[nt][0] * inv0, oacc[nt][1] * inv0);
        *(__half2*)&O[packIdx(b * S_ + row1, col, 16)] =
            __floats2half2_rn(oacc[nt][2] * inv1, oacc[nt][3] * inv1);
    }
}

// ---------------------------------------------------------------------------
// Fused residual + LayerNorm. Optional packed fp16 second copy (K=1024).
// ---------------------------------------------------------------------------
__global__ void ln_kernel(const float* __restrict__ A,
                          const float* __restrict__ R,
                          const float* __restrict__ G,
                          const float* __restrict__ Be,
                          float* __restrict__ Out,
                          __half* __restrict__ OutH)
{
    const int row = blockIdx.x;
    const int tid = threadIdx.x;
    const long long base = (long long)row * D_;

    float4 va = *(const float4*)&A[base + tid * 4];
    float4 vb = *(const float4*)&R[base + tid * 4];
    float4 v = make_float4(va.x + vb.x, va.y + vb.y, va.z + vb.z, va.w + vb.w);

    float s = v.x + v.y + v.z + v.w;
    float ss = v.x * v.x + v.y * v.y + v.z * v.z + v.w * v.w;

    __shared__ float rs_[8], rss_[8];
#pragma unroll
    for (int off = 16; off >= 1; off >>= 1) {
        s += __shfl_xor_sync(0xffffffffu, s, off);
        ss += __shfl_xor_sync(0xffffffffu, ss, off);
    }
    int warp = tid >> 5, lane = tid & 31;
    if (lane == 0) { rs_[warp] = s; rss_[warp] = ss; }
    __syncthreads();
    if (warp == 0) {
        s = (lane < 8) ? rs_[lane] : 0.0f;
        ss = (lane < 8) ? rss_[lane] : 0.0f;
#pragma unroll
        for (int off = 4; off >= 1; off >>= 1) {
            s += __shfl_xor_sync(0xffffffffu, s, off);
            ss += __shfl_xor_sync(0xffffffffu, ss, off);
        }
        if (lane == 0) { rs_[0] = s; rss_[0] = ss; }
    }
    __syncthreads();
    s = rs_[0]; ss = rss_[0];

    const float mu = s * (1.0f / 1024.0f);
    const float var = ss * (1.0f / 1024.0f) - mu * mu;
    const float rstd = rsqrtf(var + 1e-5f);

    float4 g4 = *(const float4*)&G[tid * 4];
    float4 b4 = *(const float4*)&Be[tid * 4];
    float4 ov;
    ov.x = (v.x - mu) * rstd * g4.x + b4.x;
    ov.y = (v.y - mu) * rstd * g4.y + b4.y;
    ov.z = (v.z - mu) * rstd * g4.z + b4.z;
    ov.w = (v.w - mu) * rstd * g4.w + b4.w;
    *(float4*)&Out[base + tid * 4] = ov;
    if (OutH) {
        __half* o = OutH + packIdx(row, tid * 4, 16);
        *(__half2*)o       = __floats2half2_rn(ov.x, ov.y);
        *(__half2*)(o + 2) = __floats2half2_rn(ov.z, ov.w);
    }
}

// ---------------------------------------------------------------------------
extern "C" void kernel_launch(void* const* d_in, const int* in_sizes, int n_in,
                              void* d_out, int out_size)
{
    (void)in_sizes; (void)n_in; (void)out_size;
    const float* x     = (const float*)d_in[0];
    const float* Wqkv  = (const float*)d_in[1];
    const float* Wproj = (const float*)d_in[2];
    const float* bproj = (const float*)d_in[3];
    const float* ln1g  = (const float*)d_in[4];
    const float* ln1b  = (const float*)d_in[5];
    const float* ln2g  = (const float*)d_in[6];
    const float* ln2b  = (const float*)d_in[7];
    const float* W1    = (const float*)d_in[8];
    const float* b1    = (const float*)d_in[9];
    const float* W2    = (const float*)d_in[10];
    const float* b2    = (const float*)d_in[11];
    float* out = (float*)d_out;

    float* scratch = nullptr;
    cudaGetSymbolAddress((void**)&scratch, g_scratch);

    float* PROJ = scratch + OFF_PROJ;
    float* LN1  = scratch + OFF_LN1;
    float* MLP  = scratch + OFF_MLP;

    __half* hbase  = (__half*)(scratch + FLOAT_END);
    __half* QH     = hbase + HOFF_Q;
    __half* KH     = hbase + HOFF_K;
    __half* VH     = hbase + HOFF_V;
    __half* ATTH   = hbase + HOFF_ATT;
    __half* XH     = hbase + HOFF_X;
    __half* LN1H   = hbase + HOFF_LN1;
    __half* WQKVH  = hbase + HOFF_WQKV;
    __half* WPROJH = hbase + HOFF_WPROJ;
    __half* W1H    = hbase + HOFF_W1;
    __half* W2H    = hbase + HOFF_W2;
    __half* FFHH   = hbase + HOFF_FFH;

    cudaFuncSetAttribute(hgemm_kernel,
                         cudaFuncAttributeMaxDynamicSharedMemorySize, HB_SMEM_BYTES);
    cudaFuncSetAttribute(flash_f16_kernel,
                         cudaFuncAttributeMaxDynamicSharedMemorySize, FA_SMEM_BYTES);

    // 0) fused fp16 conversion prologue (single launch)
    prologue_kernel<<<20480, 256>>>(x, Wqkv, Wproj, W1, W2,
                                    XH, WQKVH, WPROJH, W1H, W2H);

    // 1) QKV projection -> fp16 Q/K/V (flat)
    hgemm_kernel<<<dim3(24, 64), 256, HB_SMEM_BYTES>>>(
        XH, WQKVH, nullptr, nullptr, nullptr, 3072, 1024, 2, QH, KH, VH);

    // 2) causal flash attention -> fp16 ATT (packed)
    flash_f16_kernel<<<dim3(16, 64), 256, FA_SMEM_BYTES>>>(QH, KH, VH, ATTH);

    // 3) output projection + bias -> fp32 flat
    hgemm_kernel<<<dim3(8, 64), 256, HB_SMEM_BYTES>>>(
        ATTH, WPROJH, bproj, PROJ, nullptr, 1024, 1024, 0, nullptr, nullptr, nullptr);

    // 4) residual + LN1 (fp32 + packed fp16 copy)
    ln_kernel<<<8192, 256>>>(x, PROJ, ln1g, ln1b, LN1, LN1H);

    // 5) MLP up + bias + GELU -> fp16 packed
    hgemm_kernel<<<dim3(32, 64), 256, HB_SMEM_BYTES>>>(
        LN1H, W1H, b1, nullptr, FFHH, 4096, 1024, 1, nullptr, nullptr, nullptr);

    // 6) MLP down + bias -> fp32 flat
    hgemm_kernel<<<dim3(8, 64), 256, HB_SMEM_BYTES>>>(
        FFHH, W2H, b2, MLP, nullptr, 1024, 4096, 0, nullptr, nullptr, nullptr);

    // 7) residual + LN2 -> output
    ln_kernel<<<8192, 256>>>(LN1, MLP, ln2g, ln2b, out, nullptr);
}